// round 6
// baseline (speedup 1.0000x reference)
#include <cuda_runtime.h>

#define CCH 32
#define HH  256
#define WW  512
#define KK  10
#define HWPIX (HH*WW)

#define NSM   148
#define NWAVE 28            // ceil(4096 / 148)
#define NTILE 4096          // HWPIX / 32 pixels per tile

// Transposed [H,W,C] copy of right (channels contiguous) — static scratch.
__device__ float g_right_t[HWPIX * CCH];

// [C,H,W] -> [H,W,C], float4 on both global sides.
__global__ __launch_bounds__(1024) void transpose_chw_hwc(const float* __restrict__ right) {
    __shared__ float tile[32][129];
    const int h  = blockIdx.y;
    const int w0 = blockIdx.x * 128;
    const int tx = threadIdx.x, ty = threadIdx.y;

    const float4 v = *(const float4*)(right + (size_t)ty * HWPIX + h * WW + w0 + 4 * tx);
    tile[ty][4*tx + 0] = v.x;
    tile[ty][4*tx + 1] = v.y;
    tile[ty][4*tx + 2] = v.z;
    tile[ty][4*tx + 3] = v.w;
    __syncthreads();

    const int t  = ty * 32 + tx;
    const int wl = t >> 3;
    const int cq = t & 7;
    float4 o;
    o.x = tile[4*cq + 0][wl];
    o.y = tile[4*cq + 1][wl];
    o.z = tile[4*cq + 2][wl];
    o.w = tile[4*cq + 3][wl];
    *(float4*)(g_right_t + (size_t)(h * WW + w0 + wl) * CCH + 4 * cq) = o;
}

// Broadcast offset plane p (0..9 = ox[k], 10..19 = oy[k]) within 8-lane group.
#define BCAST(p) __shfl_sync(0xffffffffu, ((p) < 8 ? o0 : ((p) < 16 ? o1 : o2)), \
                             (lane & 24) | ((p) & 7))

__global__ __launch_bounds__(256) void eval_kernel(
    const float* __restrict__ left,
    const float* __restrict__ offx,
    const float* __restrict__ offy,
    float* __restrict__ out)
{
    // SM-locality remap: co-resident blocks (same placement class bid%148,
    // consecutive waves) get ADJACENT tiles -> shared sliding L1 window.
    const int cls  = blockIdx.x % NSM;
    const int wv   = blockIdx.x / NSM;
    const int tileid = cls * NWAVE + wv;
    if (tileid >= NTILE) return;

    const int lane = threadIdx.x & 31;
    const int j    = lane & 7;
    const int warp = threadIdx.x >> 5;
    const int pix  = tileid * 32 + warp * 4 + (lane >> 3);
    const int h = pix >> 9;
    const int w = pix & (WW - 1);

    const float lv0 = left[(4*j + 0) * HWPIX + pix];
    const float lv1 = left[(4*j + 1) * HWPIX + pix];
    const float lv2 = left[(4*j + 2) * HWPIX + pix];
    const float lv3 = left[(4*j + 3) * HWPIX + pix];

    const float o0 = offx[j * HWPIX + pix];
    const float o1 = (j < 2) ? offx[(j + 8) * HWPIX + pix]
                             : offy[(j - 2) * HWPIX + pix];
    const float o2 = (j < 4) ? offy[(j + 6) * HWPIX + pix] : 0.0f;

    const float4* __restrict__ rt = (const float4*)g_right_t;
    const float hf = (float)HH;
    const float wfl = (float)w, hfl = (float)h;
    float s[KK];

    #pragma unroll
    for (int k = 0; k < KK; k++) {
        const float ox_k = BCAST(k);
        const float oy_k = BCAST(k + KK);

        // clip->normalize->unnormalize == rx-0.5 exactly in fp32.
        // offset_x >= 0 so the upper x-clamp is a no-op.
        const float rx = fmaxf(wfl - ox_k, 0.0f);
        const float ry = fminf(fmaxf(hfl - oy_k, 0.0f), hf - 1.0f);
        const float ix = rx - 0.5f;
        const float iy = ry - 0.5f;

        const float x0f = floorf(ix), y0f = floorf(iy);
        const int x0 = (int)x0f, y0 = (int)y0f;      // x0 in [-1,510], y0 in [-1,254]
        const float wx1 = ix - x0f;
        const float wy1 = iy - y0f;
        float wx0 = 1.0f - wx1;
        float wy0 = 1.0f - wy1;
        if (x0 < 0) wx0 = 0.0f;                      // only low edge can be invalid
        if (y0 < 0) wy0 = 0.0f;
        const int x0c = max(x0, 0);
        const int y0c = max(y0, 0);
        const int x1 = x0 + 1, y1 = y0 + 1;          // always in range

        const float w00 = wx0 * wy0, w01 = wx1 * wy0;
        const float w10 = wx0 * wy1, w11 = wx1 * wy1;

        // 4 independent address chains (ILP), 1 wavefront each
        const float4 g00 = rt[(y0c * WW + x0c) * 8 + j];
        const float4 g01 = rt[(y0c * WW + x1 ) * 8 + j];
        const float4 g10 = rt[(y1  * WW + x0c) * 8 + j];
        const float4 g11 = rt[(y1  * WW + x1 ) * 8 + j];

        float d;
        {
            float t0 = w00*g00.x + w01*g01.x + w10*g10.x + w11*g11.x;
            float t1 = w00*g00.y + w01*g01.y + w10*g10.y + w11*g11.y;
            float t2 = w00*g00.z + w01*g01.z + w10*g10.z + w11*g11.z;
            float t3 = w00*g00.w + w01*g01.w + w10*g10.w + w11*g11.w;
            d = fabsf(lv0 - t0) + fabsf(lv1 - t1) + fabsf(lv2 - t2) + fabsf(lv3 - t3);
        }

        d += __shfl_xor_sync(0xffffffffu, d, 4);
        d += __shfl_xor_sync(0xffffffffu, d, 2);
        d += __shfl_xor_sync(0xffffffffu, d, 1);

        s[k] = d * (-10000.0f / 32.0f);
    }

    // softmax over K (redundant per lane; iterations independent -> ILP)
    float m = s[0];
    #pragma unroll
    for (int k = 1; k < KK; k++) m = fmaxf(m, s[k]);
    float denom = 0.0f;
    #pragma unroll
    for (int k = 0; k < KK; k++) { s[k] = __expf(s[k] - m); denom += s[k]; }
    const float inv = 1.0f / denom;

    float ox_acc = 0.0f, oy_acc = 0.0f;
    #pragma unroll
    for (int k = 0; k < KK; k++) {
        const float wk = s[k] * inv;
        ox_acc += BCAST(k)      * wk;
        oy_acc += BCAST(k + KK) * wk;
    }

    if (j == 0) {
        out[pix]         = ox_acc;
        out[HWPIX + pix] = oy_acc;
    }
}

extern "C" void kernel_launch(void* const* d_in, const int* in_sizes, int n_in,
                              void* d_out, int out_size) {
    const float* left  = (const float*)d_in[0];
    const float* right = (const float*)d_in[1];
    const float* offx  = (const float*)d_in[2];
    const float* offy  = (const float*)d_in[3];
    float* out = (float*)d_out;

    dim3 tb(32, 32);
    dim3 tg(WW / 128, HH);
    transpose_chw_hwc<<<tg, tb>>>(right);

    // 148 placement classes x 28 waves; blocks beyond NTILE exit immediately
    eval_kernel<<<NSM * NWAVE, 256>>>(left, offx, offy, out);
}

// round 7
// speedup vs baseline: 1.0112x; 1.0112x over previous
#include <cuda_runtime.h>

#define CCH 32
#define HH  256
#define WW  512
#define KK  10
#define HWPIX (HH*WW)

// Transposed [H,W,C] copy of right (channels contiguous) — static scratch.
__device__ float g_right_t[HWPIX * CCH];

// [C,H,W] -> [H,W,C], float4 on both global sides.
__global__ __launch_bounds__(1024) void transpose_chw_hwc(const float* __restrict__ right) {
    __shared__ float tile[32][129];
    const int h  = blockIdx.y;
    const int w0 = blockIdx.x * 128;
    const int tx = threadIdx.x, ty = threadIdx.y;

    const float4 v = *(const float4*)(right + (size_t)ty * HWPIX + h * WW + w0 + 4 * tx);
    tile[ty][4*tx + 0] = v.x;
    tile[ty][4*tx + 1] = v.y;
    tile[ty][4*tx + 2] = v.z;
    tile[ty][4*tx + 3] = v.w;
    __syncthreads();

    const int t  = ty * 32 + tx;
    const int wl = t >> 3;
    const int cq = t & 7;
    float4 o;
    o.x = tile[4*cq + 0][wl];
    o.y = tile[4*cq + 1][wl];
    o.z = tile[4*cq + 2][wl];
    o.w = tile[4*cq + 3][wl];
    *(float4*)(g_right_t + (size_t)(h * WW + w0 + wl) * CCH + 4 * cq) = o;
}

// Broadcast offset plane p (0..9 = ox[k], 10..19 = oy[k]) within 8-lane group.
#define BCAST(p) __shfl_sync(0xffffffffu, ((p) < 8 ? o0 : ((p) < 16 ? o1 : o2)), \
                             (lane & 24) | ((p) & 7))

// Coords/weights/addresses for candidate kk (compile-time under unroll).
#define COORD(kk, A00,A01,A10,A11, W00,W01,W10,W11) do {                      \
    const float ox_k = BCAST(kk);                                             \
    const float oy_k = BCAST((kk) + KK);                                      \
    /* clip->normalize->unnormalize == r-0.5 exactly in fp32;                 \
       offset_x >= 0 so the upper x-clamp is a no-op. */                      \
    const float rx_ = fmaxf(wfl - ox_k, 0.0f);                                \
    const float ry_ = fminf(fmaxf(hfl - oy_k, 0.0f), hf - 1.0f);              \
    const float ix_ = rx_ - 0.5f, iy_ = ry_ - 0.5f;                           \
    const float x0f = floorf(ix_), y0f = floorf(iy_);                         \
    const int x0 = (int)x0f, y0 = (int)y0f;   /* x0>=-1, y0>=-1 */            \
    const float wx1 = ix_ - x0f, wy1 = iy_ - y0f;                             \
    float wx0 = 1.0f - wx1, wy0 = 1.0f - wy1;                                 \
    if (x0 < 0) wx0 = 0.0f;                   /* only low edge invalid */     \
    if (y0 < 0) wy0 = 0.0f;                                                   \
    const int x0c = max(x0, 0), y0c = max(y0, 0);                             \
    const int x1 = x0 + 1, y1 = y0 + 1;       /* always in range */           \
    W00 = wx0 * wy0; W01 = wx1 * wy0; W10 = wx0 * wy1; W11 = wx1 * wy1;       \
    A00 = (y0c * WW + x0c) * 8 + j;                                           \
    A01 = (y0c * WW + x1 ) * 8 + j;                                           \
    A10 = (y1  * WW + x0c) * 8 + j;                                           \
    A11 = (y1  * WW + x1 ) * 8 + j;                                           \
} while (0)

__global__ __launch_bounds__(256) void eval_kernel(
    const float* __restrict__ left,
    const float* __restrict__ offx,
    const float* __restrict__ offy,
    float* __restrict__ out)
{
    const int lane = threadIdx.x & 31;
    const int j    = lane & 7;
    const int warp = threadIdx.x >> 5;
    const int pix  = blockIdx.x * 32 + warp * 4 + (lane >> 3);
    const int h = pix >> 9;
    const int w = pix & (WW - 1);

    const float lv0 = left[(4*j + 0) * HWPIX + pix];
    const float lv1 = left[(4*j + 1) * HWPIX + pix];
    const float lv2 = left[(4*j + 2) * HWPIX + pix];
    const float lv3 = left[(4*j + 3) * HWPIX + pix];

    const float o0 = offx[j * HWPIX + pix];
    const float o1 = (j < 2) ? offx[(j + 8) * HWPIX + pix]
                             : offy[(j - 2) * HWPIX + pix];
    const float o2 = (j < 4) ? offy[(j + 6) * HWPIX + pix] : 0.0f;

    const float4* __restrict__ rt = (const float4*)g_right_t;
    const float hf = (float)HH;
    const float wfl = (float)w, hfl = (float)h;
    float s[KK];

    // ---- software pipeline: keep k+1's 4 corner loads in flight while
    //      consuming k's (halves the per-warp critical path) ----
    int   a00, a01, a10, a11;
    float w00, w01, w10, w11;
    COORD(0, a00, a01, a10, a11, w00, w01, w10, w11);
    float4 g00 = rt[a00], g01 = rt[a01], g10 = rt[a10], g11 = rt[a11];

    #pragma unroll
    for (int k = 0; k < KK; k++) {
        int   b00, b01, b10, b11;
        float v00, v01, v10, v11;
        float4 n00, n01, n10, n11;
        if (k + 1 < KK) {
            COORD(k + 1, b00, b01, b10, b11, v00, v01, v10, v11);
            n00 = rt[b00]; n01 = rt[b01]; n10 = rt[b10]; n11 = rt[b11];
        }

        float t0 = w00*g00.x + w01*g01.x + w10*g10.x + w11*g11.x;
        float t1 = w00*g00.y + w01*g01.y + w10*g10.y + w11*g11.y;
        float t2 = w00*g00.z + w01*g01.z + w10*g10.z + w11*g11.z;
        float t3 = w00*g00.w + w01*g01.w + w10*g10.w + w11*g11.w;
        float d  = fabsf(lv0 - t0) + fabsf(lv1 - t1)
                 + fabsf(lv2 - t2) + fabsf(lv3 - t3);

        d += __shfl_xor_sync(0xffffffffu, d, 4);
        d += __shfl_xor_sync(0xffffffffu, d, 2);
        d += __shfl_xor_sync(0xffffffffu, d, 1);

        s[k] = d * (-10000.0f / 32.0f);

        if (k + 1 < KK) {
            g00 = n00; g01 = n01; g10 = n10; g11 = n11;
            w00 = v00; w01 = v01; w10 = v10; w11 = v11;
        }
    }

    // softmax over K (redundant per lane; iterations independent -> ILP)
    float m = s[0];
    #pragma unroll
    for (int k = 1; k < KK; k++) m = fmaxf(m, s[k]);
    float denom = 0.0f;
    #pragma unroll
    for (int k = 0; k < KK; k++) { s[k] = __expf(s[k] - m); denom += s[k]; }
    const float inv = 1.0f / denom;

    float ox_acc = 0.0f, oy_acc = 0.0f;
    #pragma unroll
    for (int k = 0; k < KK; k++) {
        const float wk = s[k] * inv;
        ox_acc += BCAST(k)      * wk;
        oy_acc += BCAST(k + KK) * wk;
    }

    if (j == 0) {
        out[pix]         = ox_acc;
        out[HWPIX + pix] = oy_acc;
    }
}

extern "C" void kernel_launch(void* const* d_in, const int* in_sizes, int n_in,
                              void* d_out, int out_size) {
    const float* left  = (const float*)d_in[0];
    const float* right = (const float*)d_in[1];
    const float* offx  = (const float*)d_in[2];
    const float* offy  = (const float*)d_in[3];
    float* out = (float*)d_out;

    dim3 tb(32, 32);
    dim3 tg(WW / 128, HH);
    transpose_chw_hwc<<<tg, tb>>>(right);

    eval_kernel<<<HWPIX / 32, 256>>>(left, offx, offy, out);
}